// round 13
// baseline (speedup 1.0000x reference)
#include <cuda_runtime.h>
#include <math.h>
#include <stdint.h>

// ---------------- constants ----------------
#define NIMG 8
#define NUM_CLASSES 80
#define LCH 85
#define IMGF 640.0f
#define SCORE_T 0.1f
#define NMS_T 0.6f
#define DET 100
#define OBJ_CAP 32768
#define DCAP 1024
#define TOPK 1000

// logit(0.1) = -2.197224577; margin 0.01 >> fp32 reduction-order wobble.
// Exact sigmoid recheck happens in the cand phase, so superset is safe.
#define SCAN_T (-2.2072246f)

#define NT 700             // 64KB tiles: 400 L0 + 200 L1 + 100 L2
#define GRID 592           // 4 CTAs/SM on 148 SMs — all resident (required for barriers)

// dyn smem (40960 B):
//  phase1: sw @0 (10752) | red @10752 (12288)
//  phase2: shf @0 (2048) | lg @2048 (340)
//  phase3: keys@0 8192 | payload@8192 4096 | box@12288 16384 | scr@28672 4096 | lab@32768 4096 | val@36864 4096
#define DYN_SMEM 40960

__constant__ float2 c_anchors[3][3] = {
    {{6.1f, 8.1f}, {20.6f, 12.6f}, {11.2f, 23.7f}},
    {{36.2f, 26.8f}, {25.9f, 57.2f}, {57.8f, 47.9f}},
    {{122.1f, 78.3f}, {73.7f, 143.8f}, {236.1f, 213.1f}},
};

// statically zero-initialized; reset at end of each kernel run
__device__ int g_cnt[9];       // [0]=obj cand count, [1+n]=det count
__device__ int g_work;         // tile pop counter
__device__ int g_bar1, g_bar2, g_bar3;
__device__ int g_objCand[OBJ_CAP];
__device__ float  g_detScore[NIMG][DCAP];
__device__ float4 g_detBox[NIMG][DCAP];
__device__ int    g_detInfo[NIMG][DCAP];

__device__ __forceinline__ float sigf(float x) { return 1.0f / (1.0f + expf(-x)); }

__device__ __forceinline__ int ld_acq(const int* p) {
    int v;
    asm volatile("ld.acquire.gpu.global.s32 %0, [%1];" : "=r"(v) : "l"(p) : "memory");
    return v;
}
__device__ __forceinline__ void bar_arrive(int* c) {
    __syncthreads();
    if (threadIdx.x == 0) { __threadfence(); atomicAdd(c, 1); }
}
__device__ __forceinline__ void bar_wait(int* c, int tgt) {
    if (threadIdx.x == 0) {
        while (ld_acq(c) < tgt) __nanosleep(128);
        __threadfence();
    }
    __syncthreads();
}

// ---------------- templated LDG tile processor (64KB tile, CH=16/thread) ----------------
template<int C, int HW4, int P4S, int LVL, int SWO>
__device__ __forceinline__ void ldg_tile(
    const float* __restrict__ f, const float* sw, const float* sb,
    int tLocal, float4* red, int tid)
{
    constexpr int P4     = 1 << P4S;
    constexpr int SPLITS = 256 / P4;
    constexpr int CH     = C / SPLITS;   // 16 for all levels

    int base4 = tLocal << P4S;
    int n = base4 / HW4, q4 = base4 - n * HW4;
    int pos = tid & (P4 - 1), split = tid >> P4S;
    int c0 = split * CH;
    const float4* fb = (const float4*)f + ((size_t)n * C + c0) * HW4 + q4 + pos;
    const float* swL = sw + SWO;

    float4 A0 = make_float4(0.f, 0.f, 0.f, 0.f);
    float4 A1 = A0, A2 = A0;
#pragma unroll
    for (int cc = 0; cc < CH; cc++) {
        float4 v = __ldg(fb + (size_t)cc * HW4);
        float wa = swL[c0 + cc], wb = swL[C + c0 + cc], wc = swL[2 * C + c0 + cc];
        A0.x = fmaf(v.x, wa, A0.x); A0.y = fmaf(v.y, wa, A0.y);
        A0.z = fmaf(v.z, wa, A0.z); A0.w = fmaf(v.w, wa, A0.w);
        A1.x = fmaf(v.x, wb, A1.x); A1.y = fmaf(v.y, wb, A1.y);
        A1.z = fmaf(v.z, wb, A1.z); A1.w = fmaf(v.w, wb, A1.w);
        A2.x = fmaf(v.x, wc, A2.x); A2.y = fmaf(v.y, wc, A2.y);
        A2.z = fmaf(v.z, wc, A2.z); A2.w = fmaf(v.w, wc, A2.w);
    }
    red[0 * 256 + tid] = A0;
    red[1 * 256 + tid] = A1;
    red[2 * 256 + tid] = A2;
    __syncthreads();
#pragma unroll
    for (int step = SPLITS / 2; step >= 1; step >>= 1) {
        if (tid < step * P4) {
#pragma unroll
            for (int a = 0; a < 3; a++) {
                float4 xv = red[a * 256 + tid];
                float4 yv = red[a * 256 + tid + step * P4];
                xv.x += yv.x; xv.y += yv.y; xv.z += yv.z; xv.w += yv.w;
                red[a * 256 + tid] = xv;
            }
        }
        __syncthreads();
    }
    if (tid < 3 * P4) {
        int a2 = tid >> P4S, p2 = tid & (P4 - 1);
        float bias = sb[LVL * 3 + a2];
        float4 acc = red[a2 * 256 + p2];
        float v[4] = {acc.x + bias, acc.y + bias, acc.z + bias, acc.w + bias};
        int q2 = q4 + p2;
#pragma unroll
        for (int k = 0; k < 4; k++) {
            if (v[k] > SCAN_T) {
                int p = atomicAdd(&g_cnt[0], 1);
                if (p < OBJ_CAP)
                    g_objCand[p] = (n << 17) | (LVL << 15) | (a2 << 13) | (q2 * 4 + k);
            }
        }
    }
    __syncthreads();
}

// ================= mega kernel: obj -> barrier -> cand -> barrier -> nms =================
__global__ __launch_bounds__(256, 4) void mega_kernel(
    const float* __restrict__ f0, const float* __restrict__ f1, const float* __restrict__ f2,
    const float* __restrict__ w0, const float* __restrict__ w1, const float* __restrict__ w2,
    const float* __restrict__ b0, const float* __restrict__ b1, const float* __restrict__ b2,
    const float* __restrict__ sf, float* __restrict__ out)
{
    extern __shared__ char dyn[];
    int tid = threadIdx.x;
    __shared__ float sb[9];
    __shared__ int s_tile;

    // ---------------- PHASE 1: objectness screen (work-stealing 64KB tiles) ----------------
    {
        float*  sw  = (float*)dyn;                 // 2688 floats
        float4* red = (float4*)(dyn + 10752);      // 3*256 float4

        for (int i = tid; i < 384; i += 256)
            sw[i] = __ldg(w0 + ((i >> 7) * LCH + 4) * 128 + (i & 127));
        for (int i = tid; i < 768; i += 256)
            sw[384 + i] = __ldg(w1 + ((i >> 8) * LCH + 4) * 256 + (i & 255));
        for (int i = tid; i < 1536; i += 256)
            sw[1152 + i] = __ldg(w2 + ((i >> 9) * LCH + 4) * 512 + (i & 511));
        if (tid < 9) {
            int lvl = tid / 3, a = tid - lvl * 3;
            const float* bp = lvl == 0 ? b0 : (lvl == 1 ? b1 : b2);
            sb[tid] = __ldg(bp + a * LCH + 4);
        }
        __syncthreads();

        while (true) {
            if (tid == 0) s_tile = atomicAdd(&g_work, 1);
            __syncthreads();
            int t = s_tile;
            if (t >= NT) break;
            if (t < 400)
                ldg_tile<128, 1600, 5, 0, 0>   (f0, sw, sb, t,       red, tid);
            else if (t < 600)
                ldg_tile<256, 400,  4, 1, 384> (f1, sw, sb, t - 400, red, tid);
            else
                ldg_tile<512, 100,  3, 2, 1152>(f2, sw, sb, t - 600, red, tid);
        }
    }

    bar_arrive(&g_bar1);
    bar_wait(&g_bar1, GRID);

    // ---------------- PHASE 2: full 85-channel head for candidates ----------------
    {
        float* shf = (float*)dyn;                  // 512 floats
        float* lg  = (float*)(dyn + 2048);         // 85 floats
        __shared__ float4 s_box;
        __shared__ float s_obj;
        __shared__ int s_total;

        if (tid == 0) s_total = ld_acq(&g_cnt[0]);
        __syncthreads();
        int total = s_total;
        if (total > OBJ_CAP) total = OBJ_CAP;

        int warp = tid >> 5, lane = tid & 31;

        for (int ci = blockIdx.x; ci < total; ci += GRID) {
            int pk = g_objCand[ci];
            int n = pk >> 17, level = (pk >> 15) & 3, a = (pk >> 13) & 3, hw = pk & 0x1FFF;

            const float *f, *w, *b;
            int C, HW, W, aoff;
            float stride;
            if (level == 0)      { f = f0; w = w0; b = b0; C = 128; HW = 6400; W = 80; stride = 8.f;  aoff = 0; }
            else if (level == 1) { f = f1; w = w1; b = b1; C = 256; HW = 1600; W = 40; stride = 16.f; aoff = 19200; }
            else                 { f = f2; w = w2; b = b2; C = 512; HW = 400;  W = 20; stride = 32.f; aoff = 24000; }

            for (int c = tid; c < C; c += 256)
                shf[c] = f[((size_t)n * C + c) * HW + hw];
            __syncthreads();

            const float4* shf4 = (const float4*)shf;
            int C4 = C >> 2;
            for (int row = warp; row < LCH; row += 8) {
                const float4* wr = (const float4*)(w + (size_t)(a * LCH + row) * C);
                float acc = 0.f;
                for (int c4 = lane; c4 < C4; c4 += 32) {
                    float4 wv = __ldg(wr + c4);
                    float4 fv = shf4[c4];
                    acc = fmaf(wv.x, fv.x, acc);
                    acc = fmaf(wv.y, fv.y, acc);
                    acc = fmaf(wv.z, fv.z, acc);
                    acc = fmaf(wv.w, fv.w, acc);
                }
#pragma unroll
                for (int off = 16; off > 0; off >>= 1)
                    acc += __shfl_xor_sync(0xFFFFFFFF, acc, off);
                if (lane == 0) lg[row] = acc + __ldg(b + a * LCH + row);
            }
            __syncthreads();

            if (tid == 0) {
                float px = sigf(lg[0]), py = sigf(lg[1]);
                float pw = sigf(lg[2]), ph = sigf(lg[3]);
                s_obj = sigf(lg[4]);
                int gx = hw % W, gy = hw / W;
                float2 anc = c_anchors[level][a];
                float cx = (2.f * px - 0.5f + (float)gx) * stride;
                float cy = (2.f * py - 0.5f + (float)gy) * stride;
                float bw = 4.f * pw * pw * anc.x;
                float bh = 4.f * ph * ph * anc.y;
                float x1 = cx - 0.5f * bw, y1 = cy - 0.5f * bh;
                float x2 = cx + 0.5f * bw, y2 = cy + 0.5f * bh;
                x1 = fminf(fmaxf(x1, 0.f), IMGF);
                y1 = fminf(fmaxf(y1, 0.f), IMGF);
                x2 = fminf(fmaxf(x2, 0.f), IMGF);
                y2 = fminf(fmaxf(y2, 0.f), IMGF);
                s_box = make_float4(x1, y1, x2, y2);
            }
            __syncthreads();

            if (tid < NUM_CLASSES) {
                float ob = s_obj;
                if (ob > SCORE_T) {
                    float s = ob * sigf(lg[5 + tid]);
                    if (s > SCORE_T) {
                        int pos = atomicAdd(&g_cnt[1 + n], 1);
                        if (pos < DCAP) {
                            g_detScore[n][pos] = s;
                            g_detBox[n][pos]   = s_box;
                            g_detInfo[n][pos]  = (aoff + hw * 3 + a) * NUM_CLASSES + tid;
                        }
                    }
                }
            }
            __syncthreads();
        }
    }

    bar_arrive(&g_bar2);
    if (blockIdx.x >= NIMG) return;         // only 8 blocks continue
    bar_wait(&g_bar2, GRID);

    // ---------------- PHASE 3: sort + greedy NMS + output ----------------
    {
        unsigned long long* keys = (unsigned long long*)dyn;       // 1024 * 8
        int*    payload = (int*)   (dyn + 8192);                   // 1024 * 4
        float4* box     = (float4*)(dyn + 12288);                  // 1024 * 16
        float*  scr     = (float*) (dyn + 28672);                  // 1024 * 4
        int*    lab     = (int*)   (dyn + 32768);                  // 1024 * 4
        int*    val     = (int*)   (dyn + 36864);                  // 1024 * 4
        __shared__ int picks[DET];
        __shared__ int s_sel, s_np, s_M;

        int n = blockIdx.x;
        if (tid == 0) { s_np = 0; s_M = ld_acq(&g_cnt[1 + n]); }
        __syncthreads();
        int M = s_M;
        if (M > DCAP) M = DCAP;

        if (M > 0) {
            int sortN = 2;
            while (sortN < M) sortN <<= 1;

            for (int i = tid; i < sortN; i += 256) {
                if (i < M) {
                    unsigned u = __float_as_uint(g_detScore[n][i]);
                    u = (u & 0x80000000u) ? ~u : (u | 0x80000000u);
                    keys[i] = ((unsigned long long)u << 32) | (unsigned)(0x7FFFFFFF - g_detInfo[n][i]);
                    payload[i] = i;
                } else {
                    keys[i] = 0ULL;
                    payload[i] = -1;
                }
            }
            __syncthreads();

            for (int k = 2; k <= sortN; k <<= 1) {
                for (int j = k >> 1; j > 0; j >>= 1) {
                    for (int i = tid; i < sortN; i += 256) {
                        int ixj = i ^ j;
                        if (ixj > i) {
                            bool up = ((i & k) == 0);
                            unsigned long long ka = keys[i], kb = keys[ixj];
                            bool sw = up ? (ka < kb) : (ka > kb);
                            if (sw) {
                                keys[i] = kb; keys[ixj] = ka;
                                int p = payload[i]; payload[i] = payload[ixj]; payload[ixj] = p;
                            }
                        }
                    }
                    __syncthreads();
                }
            }

            int M2 = M < TOPK ? M : TOPK;
            for (int i = tid; i < M2; i += 256) {
                int ci = payload[i];
                box[i] = g_detBox[n][ci];
                scr[i] = g_detScore[n][ci];
                lab[i] = g_detInfo[n][ci] % NUM_CLASSES;
                val[i] = 1;
            }
            __syncthreads();

            int cursor = 0;
            for (int iter = 0; iter < DET; iter++) {
                if (tid == 0) {
                    int sel = -1;
                    for (int j = cursor; j < M2; j++)
                        if (val[j]) { sel = j; break; }
                    s_sel = sel;
                    if (sel >= 0) {
                        picks[iter] = sel;
                        val[sel] = 0;
                        s_np = iter + 1;
                        cursor = sel + 1;
                    }
                }
                __syncthreads();
                int sel = s_sel;
                if (sel < 0) break;
                float4 bs = box[sel];
                int ls = lab[sel];
                float areaS = (bs.z - bs.x) * (bs.w - bs.y);
                for (int j = tid; j < M2; j += 256) {
                    if (val[j] && lab[j] == ls) {
                        float4 bj = box[j];
                        float ix1 = fmaxf(bs.x, bj.x), iy1 = fmaxf(bs.y, bj.y);
                        float ix2 = fminf(bs.z, bj.z), iy2 = fminf(bs.w, bj.w);
                        float iw = fmaxf(ix2 - ix1, 0.f), ih = fmaxf(iy2 - iy1, 0.f);
                        float inter = iw * ih;
                        float aj = (bj.z - bj.x) * (bj.w - bj.y);
                        float iou = inter / (areaS + aj - inter + 1e-7f);
                        if (iou > NMS_T) val[j] = 0;
                    }
                }
                __syncthreads();
            }
            __syncthreads();
        }
        __syncthreads();

        int np = s_np;
        float s = __ldg(sf + n);
        for (int d = tid; d < DET; d += 256) {
            float o0 = 0, o1 = 0, o2 = 0, o3 = 0, o4 = 0, o5 = 0;
            if (d < np) {
                int p = picks[d];
                float4 bbv = box[p];
                o0 = bbv.x / s; o1 = bbv.y / s; o2 = bbv.z / s; o3 = bbv.w / s;
                o4 = scr[p];
                o5 = (float)lab[p];
            }
            float* po = out + ((size_t)n * DET + d) * 6;
            po[0] = o0; po[1] = o1; po[2] = o2; po[3] = o3; po[4] = o4; po[5] = o5;
        }

        // -------- reset counters for next graph replay --------
        __syncthreads();
        if (tid == 0) {
            g_cnt[1 + n] = 0;
            __threadfence();
            atomicAdd(&g_bar3, 1);
            if (n == 0) {
                while (ld_acq(&g_bar3) < NIMG) __nanosleep(128);
                g_cnt[0] = 0;
                g_work = 0;
                g_bar1 = 0;
                g_bar2 = 0;
                g_bar3 = 0;
            }
        }
    }
}

// ---------------- launch ----------------
extern "C" void kernel_launch(void* const* d_in, const int* in_sizes, int n_in,
                              void* d_out, int out_size)
{
    const float *f0 = nullptr, *f1 = nullptr, *f2 = nullptr;
    const float *w0 = nullptr, *w1 = nullptr, *w2 = nullptr;
    const float *bbp[3] = {nullptr, nullptr, nullptr};
    const float *sf = nullptr;
    int bcount = 0;
    for (int i = 0; i < n_in; i++) {
        const float* p = (const float*)d_in[i];
        switch (in_sizes[i]) {
            case 6553600: f0 = p; break;
            case 3276800: f1 = p; break;
            case 1638400: f2 = p; break;
            case 32640:   w0 = p; break;
            case 65280:   w1 = p; break;
            case 130560:  w2 = p; break;
            case 255:     if (bcount < 3) bbp[bcount++] = p; break;
            case 8:       sf = p; break;
            default: break;
        }
    }
    const float *b0 = bbp[0], *b1 = bbp[1], *b2 = bbp[2];
    float* out = (float*)d_out;

    cudaFuncSetAttribute(mega_kernel, cudaFuncAttributeMaxDynamicSharedMemorySize, DYN_SMEM);
    mega_kernel<<<GRID, 256, DYN_SMEM>>>(f0, f1, f2, w0, w1, w2, b0, b1, b2, sf, out);
}

// round 14
// speedup vs baseline: 1.4287x; 1.4287x over previous
#include <cuda_runtime.h>
#include <math.h>
#include <stdint.h>

// ---------------- constants ----------------
#define NIMG 8
#define NUM_CLASSES 80
#define LCH 85
#define IMGF 640.0f
#define SCORE_T 0.1f
#define NMS_T 0.6f
#define DET 100
#define OBJ_CAP 32768
#define DCAP 1024
#define TOPK 1000

// logit(0.1) = -2.197224577; margin 0.01 >> fp32 reduction-order wobble.
// Exact sigmoid recheck happens in the cand phase, so superset is safe.
#define SCAN_T (-2.2072246f)

#define NT 700             // 64KB tiles: 400 L0 + 200 L1 + 100 L2
#define GRID 444           // 3 CTAs/SM on 148 SMs — all resident (required for barriers)

// dyn smem (40960 B):
//  phase1: sw @0 (10752) | red @10752 (12288)
//  phase2: shf @0 (2048) | lg @2048 (340)
//  phase3: keys@0 8192 | payload@8192 4096 | box@12288 16384 | scr@28672 4096 | lab@32768 4096 | val@36864 4096
#define DYN_SMEM 40960

__constant__ float2 c_anchors[3][3] = {
    {{6.1f, 8.1f}, {20.6f, 12.6f}, {11.2f, 23.7f}},
    {{36.2f, 26.8f}, {25.9f, 57.2f}, {57.8f, 47.9f}},
    {{122.1f, 78.3f}, {73.7f, 143.8f}, {236.1f, 213.1f}},
};

// statically zero-initialized; reset at end of each kernel run
__device__ int g_cnt[9];       // [0]=obj cand count, [1+n]=det count
__device__ int g_work;         // tile pop counter
__device__ int g_bar1, g_bar2, g_bar3;
__device__ int g_objCand[OBJ_CAP];
__device__ float  g_detScore[NIMG][DCAP];
__device__ float4 g_detBox[NIMG][DCAP];
__device__ int    g_detInfo[NIMG][DCAP];

__device__ __forceinline__ float sigf(float x) { return 1.0f / (1.0f + expf(-x)); }

__device__ __forceinline__ int ld_acq(const int* p) {
    int v;
    asm volatile("ld.acquire.gpu.global.s32 %0, [%1];" : "=r"(v) : "l"(p) : "memory");
    return v;
}
__device__ __forceinline__ void bar_arrive(int* c) {
    __syncthreads();
    if (threadIdx.x == 0) { __threadfence(); atomicAdd(c, 1); }
}
__device__ __forceinline__ void bar_wait(int* c, int tgt) {
    if (threadIdx.x == 0) {
        while (ld_acq(c) < tgt) __nanosleep(128);
        __threadfence();
    }
    __syncthreads();
}

// ---------------- templated LDG tile processor (64KB tile, CH=16/thread) ----------------
template<int C, int HW4, int P4S, int LVL, int SWO>
__device__ __forceinline__ void ldg_tile(
    const float* __restrict__ f, const float* sw, const float* sb,
    int tLocal, float4* red, int tid)
{
    constexpr int P4     = 1 << P4S;
    constexpr int SPLITS = 256 / P4;
    constexpr int CH     = C / SPLITS;   // 16 for all levels

    int base4 = tLocal << P4S;
    int n = base4 / HW4, q4 = base4 - n * HW4;
    int pos = tid & (P4 - 1), split = tid >> P4S;
    int c0 = split * CH;
    const float4* fb = (const float4*)f + ((size_t)n * C + c0) * HW4 + q4 + pos;
    const float* swL = sw + SWO;

    float4 A0 = make_float4(0.f, 0.f, 0.f, 0.f);
    float4 A1 = A0, A2 = A0;
#pragma unroll
    for (int cc = 0; cc < CH; cc++) {
        float4 v = __ldg(fb + (size_t)cc * HW4);
        float wa = swL[c0 + cc], wb = swL[C + c0 + cc], wc = swL[2 * C + c0 + cc];
        A0.x = fmaf(v.x, wa, A0.x); A0.y = fmaf(v.y, wa, A0.y);
        A0.z = fmaf(v.z, wa, A0.z); A0.w = fmaf(v.w, wa, A0.w);
        A1.x = fmaf(v.x, wb, A1.x); A1.y = fmaf(v.y, wb, A1.y);
        A1.z = fmaf(v.z, wb, A1.z); A1.w = fmaf(v.w, wb, A1.w);
        A2.x = fmaf(v.x, wc, A2.x); A2.y = fmaf(v.y, wc, A2.y);
        A2.z = fmaf(v.z, wc, A2.z); A2.w = fmaf(v.w, wc, A2.w);
    }
    red[0 * 256 + tid] = A0;
    red[1 * 256 + tid] = A1;
    red[2 * 256 + tid] = A2;
    __syncthreads();
#pragma unroll
    for (int step = SPLITS / 2; step >= 1; step >>= 1) {
        if (tid < step * P4) {
#pragma unroll
            for (int a = 0; a < 3; a++) {
                float4 xv = red[a * 256 + tid];
                float4 yv = red[a * 256 + tid + step * P4];
                xv.x += yv.x; xv.y += yv.y; xv.z += yv.z; xv.w += yv.w;
                red[a * 256 + tid] = xv;
            }
        }
        __syncthreads();
    }
    if (tid < 3 * P4) {
        int a2 = tid >> P4S, p2 = tid & (P4 - 1);
        float bias = sb[LVL * 3 + a2];
        float4 acc = red[a2 * 256 + p2];
        float v[4] = {acc.x + bias, acc.y + bias, acc.z + bias, acc.w + bias};
        int q2 = q4 + p2;
#pragma unroll
        for (int k = 0; k < 4; k++) {
            if (v[k] > SCAN_T) {
                int p = atomicAdd(&g_cnt[0], 1);
                if (p < OBJ_CAP)
                    g_objCand[p] = (n << 17) | (LVL << 15) | (a2 << 13) | (q2 * 4 + k);
            }
        }
    }
    __syncthreads();
}

// ================= mega kernel: obj -> barrier -> cand -> barrier -> nms =================
__global__ __launch_bounds__(256, 3) void mega_kernel(
    const float* __restrict__ f0, const float* __restrict__ f1, const float* __restrict__ f2,
    const float* __restrict__ w0, const float* __restrict__ w1, const float* __restrict__ w2,
    const float* __restrict__ b0, const float* __restrict__ b1, const float* __restrict__ b2,
    const float* __restrict__ sf, float* __restrict__ out)
{
    extern __shared__ char dyn[];
    int tid = threadIdx.x;
    __shared__ float sb[9];
    __shared__ int s_tile;

    // ---------------- PHASE 1: objectness screen (work-stealing 64KB tiles) ----------------
    {
        float*  sw  = (float*)dyn;                 // 2688 floats
        float4* red = (float4*)(dyn + 10752);      // 3*256 float4

        for (int i = tid; i < 384; i += 256)
            sw[i] = __ldg(w0 + ((i >> 7) * LCH + 4) * 128 + (i & 127));
        for (int i = tid; i < 768; i += 256)
            sw[384 + i] = __ldg(w1 + ((i >> 8) * LCH + 4) * 256 + (i & 255));
        for (int i = tid; i < 1536; i += 256)
            sw[1152 + i] = __ldg(w2 + ((i >> 9) * LCH + 4) * 512 + (i & 511));
        if (tid < 9) {
            int lvl = tid / 3, a = tid - lvl * 3;
            const float* bp = lvl == 0 ? b0 : (lvl == 1 ? b1 : b2);
            sb[tid] = __ldg(bp + a * LCH + 4);
        }
        __syncthreads();

        while (true) {
            if (tid == 0) s_tile = atomicAdd(&g_work, 1);
            __syncthreads();
            int t = s_tile;
            if (t >= NT) break;
            if (t < 400)
                ldg_tile<128, 1600, 5, 0, 0>   (f0, sw, sb, t,       red, tid);
            else if (t < 600)
                ldg_tile<256, 400,  4, 1, 384> (f1, sw, sb, t - 400, red, tid);
            else
                ldg_tile<512, 100,  3, 2, 1152>(f2, sw, sb, t - 600, red, tid);
        }
    }

    bar_arrive(&g_bar1);
    bar_wait(&g_bar1, GRID);

    // ---------------- PHASE 2: full 85-channel head for candidates ----------------
    {
        float* shf = (float*)dyn;                  // 512 floats
        float* lg  = (float*)(dyn + 2048);         // 85 floats
        __shared__ float4 s_box;
        __shared__ float s_obj;
        __shared__ int s_total;

        if (tid == 0) s_total = ld_acq(&g_cnt[0]);
        __syncthreads();
        int total = s_total;
        if (total > OBJ_CAP) total = OBJ_CAP;

        int warp = tid >> 5, lane = tid & 31;

        for (int ci = blockIdx.x; ci < total; ci += GRID) {
            int pk = g_objCand[ci];
            int n = pk >> 17, level = (pk >> 15) & 3, a = (pk >> 13) & 3, hw = pk & 0x1FFF;

            const float *f, *w, *b;
            int C, HW, W, aoff;
            float stride;
            if (level == 0)      { f = f0; w = w0; b = b0; C = 128; HW = 6400; W = 80; stride = 8.f;  aoff = 0; }
            else if (level == 1) { f = f1; w = w1; b = b1; C = 256; HW = 1600; W = 40; stride = 16.f; aoff = 19200; }
            else                 { f = f2; w = w2; b = b2; C = 512; HW = 400;  W = 20; stride = 32.f; aoff = 24000; }

            for (int c = tid; c < C; c += 256)
                shf[c] = f[((size_t)n * C + c) * HW + hw];
            __syncthreads();

            const float4* shf4 = (const float4*)shf;
            int C4 = C >> 2;
            for (int row = warp; row < LCH; row += 8) {
                const float4* wr = (const float4*)(w + (size_t)(a * LCH + row) * C);
                float acc = 0.f;
                for (int c4 = lane; c4 < C4; c4 += 32) {
                    float4 wv = __ldg(wr + c4);
                    float4 fv = shf4[c4];
                    acc = fmaf(wv.x, fv.x, acc);
                    acc = fmaf(wv.y, fv.y, acc);
                    acc = fmaf(wv.z, fv.z, acc);
                    acc = fmaf(wv.w, fv.w, acc);
                }
#pragma unroll
                for (int off = 16; off > 0; off >>= 1)
                    acc += __shfl_xor_sync(0xFFFFFFFF, acc, off);
                if (lane == 0) lg[row] = acc + __ldg(b + a * LCH + row);
            }
            __syncthreads();

            if (tid == 0) {
                float px = sigf(lg[0]), py = sigf(lg[1]);
                float pw = sigf(lg[2]), ph = sigf(lg[3]);
                s_obj = sigf(lg[4]);
                int gx = hw % W, gy = hw / W;
                float2 anc = c_anchors[level][a];
                float cx = (2.f * px - 0.5f + (float)gx) * stride;
                float cy = (2.f * py - 0.5f + (float)gy) * stride;
                float bw = 4.f * pw * pw * anc.x;
                float bh = 4.f * ph * ph * anc.y;
                float x1 = cx - 0.5f * bw, y1 = cy - 0.5f * bh;
                float x2 = cx + 0.5f * bw, y2 = cy + 0.5f * bh;
                x1 = fminf(fmaxf(x1, 0.f), IMGF);
                y1 = fminf(fmaxf(y1, 0.f), IMGF);
                x2 = fminf(fmaxf(x2, 0.f), IMGF);
                y2 = fminf(fmaxf(y2, 0.f), IMGF);
                s_box = make_float4(x1, y1, x2, y2);
            }
            __syncthreads();

            if (tid < NUM_CLASSES) {
                float ob = s_obj;
                if (ob > SCORE_T) {
                    float s = ob * sigf(lg[5 + tid]);
                    if (s > SCORE_T) {
                        int pos = atomicAdd(&g_cnt[1 + n], 1);
                        if (pos < DCAP) {
                            g_detScore[n][pos] = s;
                            g_detBox[n][pos]   = s_box;
                            g_detInfo[n][pos]  = (aoff + hw * 3 + a) * NUM_CLASSES + tid;
                        }
                    }
                }
            }
            __syncthreads();
        }
    }

    bar_arrive(&g_bar2);
    if (blockIdx.x >= NIMG) return;         // only 8 blocks continue
    bar_wait(&g_bar2, GRID);

    // ---------------- PHASE 3: sort + greedy NMS + output ----------------
    {
        unsigned long long* keys = (unsigned long long*)dyn;       // 1024 * 8
        int*    payload = (int*)   (dyn + 8192);                   // 1024 * 4
        float4* box     = (float4*)(dyn + 12288);                  // 1024 * 16
        float*  scr     = (float*) (dyn + 28672);                  // 1024 * 4
        int*    lab     = (int*)   (dyn + 32768);                  // 1024 * 4
        int*    val     = (int*)   (dyn + 36864);                  // 1024 * 4
        __shared__ int picks[DET];
        __shared__ int s_sel, s_np, s_M;

        int n = blockIdx.x;
        if (tid == 0) { s_np = 0; s_M = ld_acq(&g_cnt[1 + n]); }
        __syncthreads();
        int M = s_M;
        if (M > DCAP) M = DCAP;

        if (M > 0) {
            int sortN = 2;
            while (sortN < M) sortN <<= 1;

            for (int i = tid; i < sortN; i += 256) {
                if (i < M) {
                    unsigned u = __float_as_uint(g_detScore[n][i]);
                    u = (u & 0x80000000u) ? ~u : (u | 0x80000000u);
                    keys[i] = ((unsigned long long)u << 32) | (unsigned)(0x7FFFFFFF - g_detInfo[n][i]);
                    payload[i] = i;
                } else {
                    keys[i] = 0ULL;
                    payload[i] = -1;
                }
            }
            __syncthreads();

            for (int k = 2; k <= sortN; k <<= 1) {
                for (int j = k >> 1; j > 0; j >>= 1) {
                    for (int i = tid; i < sortN; i += 256) {
                        int ixj = i ^ j;
                        if (ixj > i) {
                            bool up = ((i & k) == 0);
                            unsigned long long ka = keys[i], kb = keys[ixj];
                            bool sw = up ? (ka < kb) : (ka > kb);
                            if (sw) {
                                keys[i] = kb; keys[ixj] = ka;
                                int p = payload[i]; payload[i] = payload[ixj]; payload[ixj] = p;
                            }
                        }
                    }
                    __syncthreads();
                }
            }

            int M2 = M < TOPK ? M : TOPK;
            for (int i = tid; i < M2; i += 256) {
                int ci = payload[i];
                box[i] = g_detBox[n][ci];
                scr[i] = g_detScore[n][ci];
                lab[i] = g_detInfo[n][ci] % NUM_CLASSES;
                val[i] = 1;
            }
            __syncthreads();

            int cursor = 0;
            for (int iter = 0; iter < DET; iter++) {
                if (tid == 0) {
                    int sel = -1;
                    for (int j = cursor; j < M2; j++)
                        if (val[j]) { sel = j; break; }
                    s_sel = sel;
                    if (sel >= 0) {
                        picks[iter] = sel;
                        val[sel] = 0;
                        s_np = iter + 1;
                        cursor = sel + 1;
                    }
                }
                __syncthreads();
                int sel = s_sel;
                if (sel < 0) break;
                float4 bs = box[sel];
                int ls = lab[sel];
                float areaS = (bs.z - bs.x) * (bs.w - bs.y);
                for (int j = tid; j < M2; j += 256) {
                    if (val[j] && lab[j] == ls) {
                        float4 bj = box[j];
                        float ix1 = fmaxf(bs.x, bj.x), iy1 = fmaxf(bs.y, bj.y);
                        float ix2 = fminf(bs.z, bj.z), iy2 = fminf(bs.w, bj.w);
                        float iw = fmaxf(ix2 - ix1, 0.f), ih = fmaxf(iy2 - iy1, 0.f);
                        float inter = iw * ih;
                        float aj = (bj.z - bj.x) * (bj.w - bj.y);
                        float iou = inter / (areaS + aj - inter + 1e-7f);
                        if (iou > NMS_T) val[j] = 0;
                    }
                }
                __syncthreads();
            }
            __syncthreads();
        }
        __syncthreads();

        int np = s_np;
        float s = __ldg(sf + n);
        for (int d = tid; d < DET; d += 256) {
            float o0 = 0, o1 = 0, o2 = 0, o3 = 0, o4 = 0, o5 = 0;
            if (d < np) {
                int p = picks[d];
                float4 bbv = box[p];
                o0 = bbv.x / s; o1 = bbv.y / s; o2 = bbv.z / s; o3 = bbv.w / s;
                o4 = scr[p];
                o5 = (float)lab[p];
            }
            float* po = out + ((size_t)n * DET + d) * 6;
            po[0] = o0; po[1] = o1; po[2] = o2; po[3] = o3; po[4] = o4; po[5] = o5;
        }

        // -------- reset counters for next graph replay --------
        __syncthreads();
        if (tid == 0) {
            g_cnt[1 + n] = 0;
            __threadfence();
            atomicAdd(&g_bar3, 1);
            if (n == 0) {
                while (ld_acq(&g_bar3) < NIMG) __nanosleep(128);
                g_cnt[0] = 0;
                g_work = 0;
                g_bar1 = 0;
                g_bar2 = 0;
                g_bar3 = 0;
            }
        }
    }
}

// ---------------- launch ----------------
extern "C" void kernel_launch(void* const* d_in, const int* in_sizes, int n_in,
                              void* d_out, int out_size)
{
    const float *f0 = nullptr, *f1 = nullptr, *f2 = nullptr;
    const float *w0 = nullptr, *w1 = nullptr, *w2 = nullptr;
    const float *bbp[3] = {nullptr, nullptr, nullptr};
    const float *sf = nullptr;
    int bcount = 0;
    for (int i = 0; i < n_in; i++) {
        const float* p = (const float*)d_in[i];
        switch (in_sizes[i]) {
            case 6553600: f0 = p; break;
            case 3276800: f1 = p; break;
            case 1638400: f2 = p; break;
            case 32640:   w0 = p; break;
            case 65280:   w1 = p; break;
            case 130560:  w2 = p; break;
            case 255:     if (bcount < 3) bbp[bcount++] = p; break;
            case 8:       sf = p; break;
            default: break;
        }
    }
    const float *b0 = bbp[0], *b1 = bbp[1], *b2 = bbp[2];
    float* out = (float*)d_out;

    cudaFuncSetAttribute(mega_kernel, cudaFuncAttributeMaxDynamicSharedMemorySize, DYN_SMEM);
    mega_kernel<<<GRID, 256, DYN_SMEM>>>(f0, f1, f2, w0, w1, w2, b0, b1, b2, sf, out);
}

// round 15
// speedup vs baseline: 1.5384x; 1.0767x over previous
#include <cuda_runtime.h>
#include <math.h>
#include <stdint.h>

// ---------------- constants ----------------
#define NIMG 8
#define NUM_CLASSES 80
#define LCH 85
#define IMGF 640.0f
#define SCORE_T 0.1f
#define NMS_T 0.6f
#define DET 100
#define OBJ_CAP 32768
#define DCAP 1024
#define TOPK 1000

// logit(0.1) = -2.197224577; margin 0.01 >> fp32 reduction-order wobble.
// Exact sigmoid recheck happens in the cand phase, so superset is safe.
#define SCAN_T (-2.2072246f)

#define CN_GRID 328        // cand blocks; first NIMG continue into NMS

// dyn smem for candnms (40960 B):
//  cand: shf @0 (2048) | lg @2048 (340)
//  nms:  keys@0 8192 | payload@8192 4096 | box@12288 16384 | scr@28672 4096 | lab@32768 4096 | val@36864 4096
#define CN_SMEM 40960

__constant__ float2 c_anchors[3][3] = {
    {{6.1f, 8.1f}, {20.6f, 12.6f}, {11.2f, 23.7f}},
    {{36.2f, 26.8f}, {25.9f, 57.2f}, {57.8f, 47.9f}},
    {{122.1f, 78.3f}, {73.7f, 143.8f}, {236.1f, 213.1f}},
};

// statically zero-initialized; candnms resets everything at the end of each run
__device__ int g_cnt[9];       // [0]=obj cand count, [1+n]=det count
__device__ int g_barA, g_barB;
__device__ int g_objCand[OBJ_CAP];
__device__ float  g_detScore[NIMG][DCAP];
__device__ float4 g_detBox[NIMG][DCAP];
__device__ int    g_detInfo[NIMG][DCAP];

__device__ __forceinline__ float sigf(float x) { return 1.0f / (1.0f + expf(-x)); }

__device__ __forceinline__ int ld_acq(const int* p) {
    int v;
    asm volatile("ld.acquire.gpu.global.s32 %0, [%1];" : "=r"(v) : "l"(p) : "memory");
    return v;
}

// ------------- pass 1: obj GEMV, uniform 64KB tiles (R7, proven fastest) -------------
// Block tile = P float4-positions x C channels; CH = 16 channels/thread always.
// L0: C=128 P=32 -> 400 blocks   L1: C=256 P=16 -> 200 blocks
// L2: C=512 P=8  -> 100 blocks   total 700 uniform blocks
#define OBJ_BLOCKS 700

template<int C, int HW, int LEVEL, int P>
__device__ __forceinline__ void obj_level(
    const float* __restrict__ f, const float* __restrict__ wgt, const float* __restrict__ b,
    int blkLocal, float* sw, float4* red, float* sb)
{
    constexpr int HW4  = HW / 4;
    constexpr int STOT = 256 / P;        // total channel splits
    constexpr int CH   = C / STOT;       // = 16 channels per thread

    int tid  = threadIdx.x;
    int warp = tid >> 5, lane = tid & 31;

    for (int i = tid; i < 3 * C; i += 256) {
        int a = i / C, c = i - a * C;
        sw[i] = wgt[(a * LCH + 4) * C + c];
    }
    if (tid < 3) sb[tid] = b[tid * LCH + 4];
    __syncthreads();

    int pos   = lane % P;
    int sub   = lane / P;
    int split = warp * (32 / P) + sub;
    int c0    = split * CH;

    int id = blkLocal * P + pos;                 // flattened n*HW4+q, exact coverage
    int n = id / HW4, q = id - n * HW4;

    const float4* fb = (const float4*)f + ((size_t)n * C + c0) * HW4 + q;

    float4 A0 = make_float4(0.f, 0.f, 0.f, 0.f);
    float4 A1 = A0, A2 = A0;
#pragma unroll
    for (int cc = 0; cc < CH; cc++) {
        float4 v = __ldg(fb + (size_t)cc * HW4);
        float w0v = sw[c0 + cc], w1v = sw[C + c0 + cc], w2v = sw[2 * C + c0 + cc];
        A0.x = fmaf(v.x, w0v, A0.x); A0.y = fmaf(v.y, w0v, A0.y);
        A0.z = fmaf(v.z, w0v, A0.z); A0.w = fmaf(v.w, w0v, A0.w);
        A1.x = fmaf(v.x, w1v, A1.x); A1.y = fmaf(v.y, w1v, A1.y);
        A1.z = fmaf(v.z, w1v, A1.z); A1.w = fmaf(v.w, w1v, A1.w);
        A2.x = fmaf(v.x, w2v, A2.x); A2.y = fmaf(v.y, w2v, A2.y);
        A2.z = fmaf(v.z, w2v, A2.z); A2.w = fmaf(v.w, w2v, A2.w);
    }
    red[0 * 256 + split * P + pos] = A0;
    red[1 * 256 + split * P + pos] = A1;
    red[2 * 256 + split * P + pos] = A2;
    __syncthreads();

    if (tid < 3 * P) {
        int a2 = tid / P, p2 = tid % P;
        float4 acc = red[a2 * 256 + p2];
#pragma unroll
        for (int s2 = 1; s2 < STOT; s2++) {
            float4 r = red[a2 * 256 + s2 * P + p2];
            acc.x += r.x; acc.y += r.y; acc.z += r.z; acc.w += r.w;
        }
        float bias = sb[a2];
        int id2 = blkLocal * P + p2;
        int n2 = id2 / HW4, q2 = id2 - n2 * HW4;
        float v[4] = {acc.x + bias, acc.y + bias, acc.z + bias, acc.w + bias};
#pragma unroll
        for (int k = 0; k < 4; k++) {
            if (v[k] > SCAN_T) {
                int p = atomicAdd(&g_cnt[0], 1);
                if (p < OBJ_CAP)
                    g_objCand[p] = (n2 << 17) | (LEVEL << 15) | (a2 << 13) | (q2 * 4 + k);
            }
        }
    }
}

__global__ __launch_bounds__(256, 5) void obj_kernel(
    const float* __restrict__ f0, const float* __restrict__ f1, const float* __restrict__ f2,
    const float* __restrict__ w0, const float* __restrict__ w1, const float* __restrict__ w2,
    const float* __restrict__ b0, const float* __restrict__ b1, const float* __restrict__ b2)
{
    __shared__ float sw[3 * 512];
    __shared__ float4 red[3 * 256];
    __shared__ float sb[3];

    int blk = blockIdx.x;
    if (blk < 400)      obj_level<128, 6400, 0, 32>(f0, w0, b0, blk,       sw, red, sb);
    else if (blk < 600) obj_level<256, 1600, 1, 16>(f1, w1, b1, blk - 400, sw, red, sb);
    else                obj_level<512, 400,  2, 8 >(f2, w2, b2, blk - 600, sw, red, sb);
}

// ------------- pass 2+3 fused: cand (all blocks) -> barrier -> nms (blocks 0..7) -------------
__global__ __launch_bounds__(256) void candnms_kernel(
    const float* __restrict__ f0, const float* __restrict__ f1, const float* __restrict__ f2,
    const float* __restrict__ w0, const float* __restrict__ w1, const float* __restrict__ w2,
    const float* __restrict__ b0, const float* __restrict__ b1, const float* __restrict__ b2,
    const float* __restrict__ sf, float* __restrict__ out)
{
    extern __shared__ char dyn[];
    int tid = threadIdx.x;

    // ---------- cand phase ----------
    {
        float* shf = (float*)dyn;                  // 512 floats
        float* lg  = (float*)(dyn + 2048);         // 85 floats
        __shared__ float4 s_box;
        __shared__ float s_obj;

        int total = g_cnt[0];
        if (total > OBJ_CAP) total = OBJ_CAP;

        int warp = tid >> 5, lane = tid & 31;

        for (int ci = blockIdx.x; ci < total; ci += CN_GRID) {
            int pk = g_objCand[ci];
            int n = pk >> 17, level = (pk >> 15) & 3, a = (pk >> 13) & 3, hw = pk & 0x1FFF;

            const float *f, *w, *b;
            int C, HW, W, aoff;
            float stride;
            if (level == 0)      { f = f0; w = w0; b = b0; C = 128; HW = 6400; W = 80; stride = 8.f;  aoff = 0; }
            else if (level == 1) { f = f1; w = w1; b = b1; C = 256; HW = 1600; W = 40; stride = 16.f; aoff = 19200; }
            else                 { f = f2; w = w2; b = b2; C = 512; HW = 400;  W = 20; stride = 32.f; aoff = 24000; }

            for (int c = tid; c < C; c += 256)
                shf[c] = f[((size_t)n * C + c) * HW + hw];
            __syncthreads();

            const float4* shf4 = (const float4*)shf;
            int C4 = C >> 2;
            for (int row = warp; row < LCH; row += 8) {
                const float4* wr = (const float4*)(w + (size_t)(a * LCH + row) * C);
                float acc = 0.f;
                for (int c4 = lane; c4 < C4; c4 += 32) {
                    float4 wv = __ldg(wr + c4);
                    float4 fv = shf4[c4];
                    acc = fmaf(wv.x, fv.x, acc);
                    acc = fmaf(wv.y, fv.y, acc);
                    acc = fmaf(wv.z, fv.z, acc);
                    acc = fmaf(wv.w, fv.w, acc);
                }
#pragma unroll
                for (int off = 16; off > 0; off >>= 1)
                    acc += __shfl_xor_sync(0xFFFFFFFF, acc, off);
                if (lane == 0) lg[row] = acc + __ldg(b + a * LCH + row);
            }
            __syncthreads();

            if (tid == 0) {
                float px = sigf(lg[0]), py = sigf(lg[1]);
                float pw = sigf(lg[2]), ph = sigf(lg[3]);
                s_obj = sigf(lg[4]);
                int gx = hw % W, gy = hw / W;
                float2 anc = c_anchors[level][a];
                float cx = (2.f * px - 0.5f + (float)gx) * stride;
                float cy = (2.f * py - 0.5f + (float)gy) * stride;
                float bw = 4.f * pw * pw * anc.x;
                float bh = 4.f * ph * ph * anc.y;
                float x1 = cx - 0.5f * bw, y1 = cy - 0.5f * bh;
                float x2 = cx + 0.5f * bw, y2 = cy + 0.5f * bh;
                x1 = fminf(fmaxf(x1, 0.f), IMGF);
                y1 = fminf(fmaxf(y1, 0.f), IMGF);
                x2 = fminf(fmaxf(x2, 0.f), IMGF);
                y2 = fminf(fmaxf(y2, 0.f), IMGF);
                s_box = make_float4(x1, y1, x2, y2);
            }
            __syncthreads();

            if (tid < NUM_CLASSES) {
                float ob = s_obj;
                if (ob > SCORE_T) {
                    float s = ob * sigf(lg[5 + tid]);
                    if (s > SCORE_T) {
                        int pos = atomicAdd(&g_cnt[1 + n], 1);
                        if (pos < DCAP) {
                            g_detScore[n][pos] = s;
                            g_detBox[n][pos]   = s_box;
                            g_detInfo[n][pos]  = (aoff + hw * 3 + a) * NUM_CLASSES + tid;
                        }
                    }
                }
            }
            __syncthreads();
        }
    }

    // ---------- global arrive; non-NMS blocks exit (deadlock-free: waiters hold only 8 SMs) ----------
    __syncthreads();
    if (tid == 0) { __threadfence(); atomicAdd(&g_barA, 1); }
    if (blockIdx.x >= NIMG) return;
    if (tid == 0) {
        while (ld_acq(&g_barA) < CN_GRID) __nanosleep(128);
        __threadfence();
    }
    __syncthreads();

    // ---------- nms phase (blocks 0..7) ----------
    {
        unsigned long long* keys = (unsigned long long*)dyn;       // 1024 * 8
        int*    payload = (int*)   (dyn + 8192);                   // 1024 * 4
        float4* box     = (float4*)(dyn + 12288);                  // 1024 * 16
        float*  scr     = (float*) (dyn + 28672);                  // 1024 * 4
        int*    lab     = (int*)   (dyn + 32768);                  // 1024 * 4
        int*    val     = (int*)   (dyn + 36864);                  // 1024 * 4
        __shared__ int picks[DET];
        __shared__ int s_sel, s_np, s_M;

        int n = blockIdx.x;
        if (tid == 0) { s_np = 0; s_M = ld_acq(&g_cnt[1 + n]); }
        __syncthreads();
        int M = s_M;
        if (M > DCAP) M = DCAP;

        if (M > 0) {
            int sortN = 2;
            while (sortN < M) sortN <<= 1;

            for (int i = tid; i < sortN; i += 256) {
                if (i < M) {
                    unsigned u = __float_as_uint(g_detScore[n][i]);
                    u = (u & 0x80000000u) ? ~u : (u | 0x80000000u);
                    keys[i] = ((unsigned long long)u << 32) | (unsigned)(0x7FFFFFFF - g_detInfo[n][i]);
                    payload[i] = i;
                } else {
                    keys[i] = 0ULL;
                    payload[i] = -1;
                }
            }
            __syncthreads();

            for (int k = 2; k <= sortN; k <<= 1) {
                for (int j = k >> 1; j > 0; j >>= 1) {
                    for (int i = tid; i < sortN; i += 256) {
                        int ixj = i ^ j;
                        if (ixj > i) {
                            bool up = ((i & k) == 0);
                            unsigned long long ka = keys[i], kb = keys[ixj];
                            bool sw = up ? (ka < kb) : (ka > kb);
                            if (sw) {
                                keys[i] = kb; keys[ixj] = ka;
                                int p = payload[i]; payload[i] = payload[ixj]; payload[ixj] = p;
                            }
                        }
                    }
                    __syncthreads();
                }
            }

            int M2 = M < TOPK ? M : TOPK;
            for (int i = tid; i < M2; i += 256) {
                int ci = payload[i];
                box[i] = g_detBox[n][ci];
                scr[i] = g_detScore[n][ci];
                lab[i] = g_detInfo[n][ci] % NUM_CLASSES;
                val[i] = 1;
            }
            __syncthreads();

            int cursor = 0;
            for (int iter = 0; iter < DET; iter++) {
                if (tid == 0) {
                    int sel = -1;
                    for (int j = cursor; j < M2; j++)
                        if (val[j]) { sel = j; break; }
                    s_sel = sel;
                    if (sel >= 0) {
                        picks[iter] = sel;
                        val[sel] = 0;
                        s_np = iter + 1;
                        cursor = sel + 1;
                    }
                }
                __syncthreads();
                int sel = s_sel;
                if (sel < 0) break;
                float4 bs = box[sel];
                int ls = lab[sel];
                float areaS = (bs.z - bs.x) * (bs.w - bs.y);
                for (int j = tid; j < M2; j += 256) {
                    if (val[j] && lab[j] == ls) {
                        float4 bj = box[j];
                        float ix1 = fmaxf(bs.x, bj.x), iy1 = fmaxf(bs.y, bj.y);
                        float ix2 = fminf(bs.z, bj.z), iy2 = fminf(bs.w, bj.w);
                        float iw = fmaxf(ix2 - ix1, 0.f), ih = fmaxf(iy2 - iy1, 0.f);
                        float inter = iw * ih;
                        float aj = (bj.z - bj.x) * (bj.w - bj.y);
                        float iou = inter / (areaS + aj - inter + 1e-7f);
                        if (iou > NMS_T) val[j] = 0;
                    }
                }
                __syncthreads();
            }
            __syncthreads();
        }
        __syncthreads();

        int np = s_np;
        float s = __ldg(sf + n);
        for (int d = tid; d < DET; d += 256) {
            float o0 = 0, o1 = 0, o2 = 0, o3 = 0, o4 = 0, o5 = 0;
            if (d < np) {
                int p = picks[d];
                float4 bbv = box[p];
                o0 = bbv.x / s; o1 = bbv.y / s; o2 = bbv.z / s; o3 = bbv.w / s;
                o4 = scr[p];
                o5 = (float)lab[p];
            }
            float* po = out + ((size_t)n * DET + d) * 6;
            po[0] = o0; po[1] = o1; po[2] = o2; po[3] = o3; po[4] = o4; po[5] = o5;
        }

        // -------- reset counters for next graph replay --------
        __syncthreads();
        if (tid == 0) {
            g_cnt[1 + n] = 0;
            __threadfence();
            atomicAdd(&g_barB, 1);
            if (n == 0) {
                while (ld_acq(&g_barB) < NIMG) __nanosleep(128);
                g_cnt[0] = 0;
                g_barA = 0;
                g_barB = 0;
            }
        }
    }
}

// ---------------- launch ----------------
extern "C" void kernel_launch(void* const* d_in, const int* in_sizes, int n_in,
                              void* d_out, int out_size)
{
    const float *f0 = nullptr, *f1 = nullptr, *f2 = nullptr;
    const float *w0 = nullptr, *w1 = nullptr, *w2 = nullptr;
    const float *bbp[3] = {nullptr, nullptr, nullptr};
    const float *sf = nullptr;
    int bcount = 0;
    for (int i = 0; i < n_in; i++) {
        const float* p = (const float*)d_in[i];
        switch (in_sizes[i]) {
            case 6553600: f0 = p; break;
            case 3276800: f1 = p; break;
            case 1638400: f2 = p; break;
            case 32640:   w0 = p; break;
            case 65280:   w1 = p; break;
            case 130560:  w2 = p; break;
            case 255:     if (bcount < 3) bbp[bcount++] = p; break;
            case 8:       sf = p; break;
            default: break;
        }
    }
    const float *b0 = bbp[0], *b1 = bbp[1], *b2 = bbp[2];
    float* out = (float*)d_out;

    obj_kernel<<<OBJ_BLOCKS, 256>>>(f0, f1, f2, w0, w1, w2, b0, b1, b2);

    cudaFuncSetAttribute(candnms_kernel, cudaFuncAttributeMaxDynamicSharedMemorySize, CN_SMEM);
    candnms_kernel<<<CN_GRID, 256, CN_SMEM>>>(f0, f1, f2, w0, w1, w2, b0, b1, b2, sf, out);
}

// round 17
// speedup vs baseline: 1.6452x; 1.0694x over previous
#include <cuda_runtime.h>
#include <math.h>
#include <stdint.h>

// ---------------- constants ----------------
#define NIMG 8
#define NUM_CLASSES 80
#define LCH 85
#define IMGF 640.0f
#define SCORE_T 0.1f
#define NMS_T 0.6f
#define DET 100
#define OBJ_CAP 32768
#define DCAP 1024
#define TOPK 1000

// logit(0.1) = -2.197224577; margin 0.01 >> fp32 reduction-order wobble.
// Exact sigmoid recheck happens in the cand phase, so superset is safe.
#define SCAN_T (-2.2072246f)

#define CN_GRID 328        // cand blocks; first NIMG continue into NMS

// dyn smem for candnms (40960 B):
//  cand: shf @0 (2048) | lg @2048 (340)
//  nms:  keys@0 8192 | payload@8192 4096 | box@12288 16384 | scr@28672 4096 | lab@32768 4096 | val@36864 4096
#define CN_SMEM 40960

__constant__ float2 c_anchors[3][3] = {
    {{6.1f, 8.1f}, {20.6f, 12.6f}, {11.2f, 23.7f}},
    {{36.2f, 26.8f}, {25.9f, 57.2f}, {57.8f, 47.9f}},
    {{122.1f, 78.3f}, {73.7f, 143.8f}, {236.1f, 213.1f}},
};

// statically zero-initialized; candnms resets everything at the end of each run
__device__ int g_cnt[9];       // [0]=obj cand count, [1+n]=det count
__device__ int g_barA, g_barB;
__device__ int g_objCand[OBJ_CAP];
__device__ float  g_detScore[NIMG][DCAP];
__device__ float4 g_detBox[NIMG][DCAP];
__device__ int    g_detInfo[NIMG][DCAP];

__device__ __forceinline__ float sigf(float x) { return 1.0f / (1.0f + expf(-x)); }

__device__ __forceinline__ int ld_acq(const int* p) {
    int v;
    asm volatile("ld.acquire.gpu.global.s32 %0, [%1];" : "=r"(v) : "l"(p) : "memory");
    return v;
}

// ------------- pass 1: obj GEMV, uniform 64KB tiles (R7, proven fastest) -------------
// Block tile = P float4-positions x C channels; CH = 16 channels/thread always.
// L0: C=128 P=32 -> 400 blocks   L1: C=256 P=16 -> 200 blocks
// L2: C=512 P=8  -> 100 blocks   total 700 uniform blocks
#define OBJ_BLOCKS 700

template<int C, int HW, int LEVEL, int P>
__device__ __forceinline__ void obj_level(
    const float* __restrict__ f, const float* __restrict__ wgt, const float* __restrict__ b,
    int blkLocal, float* sw, float4* red, float* sb)
{
    constexpr int HW4  = HW / 4;
    constexpr int STOT = 256 / P;        // total channel splits
    constexpr int CH   = C / STOT;       // = 16 channels per thread

    int tid  = threadIdx.x;
    int warp = tid >> 5, lane = tid & 31;

    for (int i = tid; i < 3 * C; i += 256) {
        int a = i / C, c = i - a * C;
        sw[i] = wgt[(a * LCH + 4) * C + c];
    }
    if (tid < 3) sb[tid] = b[tid * LCH + 4];
    __syncthreads();

    int pos   = lane % P;
    int sub   = lane / P;
    int split = warp * (32 / P) + sub;
    int c0    = split * CH;

    int id = blkLocal * P + pos;                 // flattened n*HW4+q, exact coverage
    int n = id / HW4, q = id - n * HW4;

    const float4* fb = (const float4*)f + ((size_t)n * C + c0) * HW4 + q;

    float4 A0 = make_float4(0.f, 0.f, 0.f, 0.f);
    float4 A1 = A0, A2 = A0;
#pragma unroll
    for (int cc = 0; cc < CH; cc++) {
        float4 v = __ldg(fb + (size_t)cc * HW4);
        float w0v = sw[c0 + cc], w1v = sw[C + c0 + cc], w2v = sw[2 * C + c0 + cc];
        A0.x = fmaf(v.x, w0v, A0.x); A0.y = fmaf(v.y, w0v, A0.y);
        A0.z = fmaf(v.z, w0v, A0.z); A0.w = fmaf(v.w, w0v, A0.w);
        A1.x = fmaf(v.x, w1v, A1.x); A1.y = fmaf(v.y, w1v, A1.y);
        A1.z = fmaf(v.z, w1v, A1.z); A1.w = fmaf(v.w, w1v, A1.w);
        A2.x = fmaf(v.x, w2v, A2.x); A2.y = fmaf(v.y, w2v, A2.y);
        A2.z = fmaf(v.z, w2v, A2.z); A2.w = fmaf(v.w, w2v, A2.w);
    }
    red[0 * 256 + split * P + pos] = A0;
    red[1 * 256 + split * P + pos] = A1;
    red[2 * 256 + split * P + pos] = A2;
    __syncthreads();

    if (tid < 3 * P) {
        int a2 = tid / P, p2 = tid % P;
        float4 acc = red[a2 * 256 + p2];
#pragma unroll
        for (int s2 = 1; s2 < STOT; s2++) {
            float4 r = red[a2 * 256 + s2 * P + p2];
            acc.x += r.x; acc.y += r.y; acc.z += r.z; acc.w += r.w;
        }
        float bias = sb[a2];
        int id2 = blkLocal * P + p2;
        int n2 = id2 / HW4, q2 = id2 - n2 * HW4;
        float v[4] = {acc.x + bias, acc.y + bias, acc.z + bias, acc.w + bias};
#pragma unroll
        for (int k = 0; k < 4; k++) {
            if (v[k] > SCAN_T) {
                int p = atomicAdd(&g_cnt[0], 1);
                if (p < OBJ_CAP)
                    g_objCand[p] = (n2 << 17) | (LEVEL << 15) | (a2 << 13) | (q2 * 4 + k);
            }
        }
    }
}

__global__ __launch_bounds__(256, 5) void obj_kernel(
    const float* __restrict__ f0, const float* __restrict__ f1, const float* __restrict__ f2,
    const float* __restrict__ w0, const float* __restrict__ w1, const float* __restrict__ w2,
    const float* __restrict__ b0, const float* __restrict__ b1, const float* __restrict__ b2)
{
    __shared__ float sw[3 * 512];
    __shared__ float4 red[3 * 256];
    __shared__ float sb[3];

    int blk = blockIdx.x;
    if (blk < 400)      obj_level<128, 6400, 0, 32>(f0, w0, b0, blk,       sw, red, sb);
    else if (blk < 600) obj_level<256, 1600, 1, 16>(f1, w1, b1, blk - 400, sw, red, sb);
    else                obj_level<512, 400,  2, 8 >(f2, w2, b2, blk - 600, sw, red, sb);
}

// ---------------- templated cand row-dots (compile-time C -> fully unrolled) ----------------
template<int C>
__device__ __forceinline__ void cand_rows(
    const float* __restrict__ w, const float* __restrict__ b, int a,
    const float4* shf4, float* lg, int warp, int lane)
{
    constexpr int K = (C / 4) / 32;      // 1 / 2 / 4 inner chunks
    for (int row = warp; row < LCH; row += 8) {
        const float4* wr = (const float4*)(w + (size_t)(a * LCH + row) * C);
        float acc = 0.f;
#pragma unroll
        for (int k = 0; k < K; k++) {
            int c4 = lane + k * 32;
            float4 wv = __ldg(wr + c4);
            float4 fv = shf4[c4];
            acc = fmaf(wv.x, fv.x, acc);
            acc = fmaf(wv.y, fv.y, acc);
            acc = fmaf(wv.z, fv.z, acc);
            acc = fmaf(wv.w, fv.w, acc);
        }
#pragma unroll
        for (int off = 16; off > 0; off >>= 1)
            acc += __shfl_xor_sync(0xFFFFFFFF, acc, off);
        if (lane == 0) lg[row] = acc + __ldg(b + a * LCH + row);
    }
}

// ------------- pass 2+3 fused: cand (all blocks) -> barrier -> nms (blocks 0..7) -------------
__global__ __launch_bounds__(256) void candnms_kernel(
    const float* __restrict__ f0, const float* __restrict__ f1, const float* __restrict__ f2,
    const float* __restrict__ w0, const float* __restrict__ w1, const float* __restrict__ w2,
    const float* __restrict__ b0, const float* __restrict__ b1, const float* __restrict__ b2,
    const float* __restrict__ sf, float* __restrict__ out)
{
    extern __shared__ char dyn[];
    int tid = threadIdx.x;

    // ---------- cand phase ----------
    {
        float* shf = (float*)dyn;                  // 512 floats
        float* lg  = (float*)(dyn + 2048);         // 85 floats
        __shared__ float4 s_box;
        __shared__ float s_obj;

        int total = g_cnt[0];
        if (total > OBJ_CAP) total = OBJ_CAP;

        int warp = tid >> 5, lane = tid & 31;

        for (int ci = blockIdx.x; ci < total; ci += CN_GRID) {
            int pk = g_objCand[ci];
            int n = pk >> 17, level = (pk >> 15) & 3, a = (pk >> 13) & 3, hw = pk & 0x1FFF;

            const float *f, *w, *b;
            int C, HW, W, aoff;
            float stride;
            if (level == 0)      { f = f0; w = w0; b = b0; C = 128; HW = 6400; W = 80; stride = 8.f;  aoff = 0; }
            else if (level == 1) { f = f1; w = w1; b = b1; C = 256; HW = 1600; W = 40; stride = 16.f; aoff = 19200; }
            else                 { f = f2; w = w2; b = b2; C = 512; HW = 400;  W = 20; stride = 32.f; aoff = 24000; }

            for (int c = tid; c < C; c += 256)
                shf[c] = f[((size_t)n * C + c) * HW + hw];
            __syncthreads();

            const float4* shf4 = (const float4*)shf;
            if (level == 0)      cand_rows<128>(w, b, a, shf4, lg, warp, lane);
            else if (level == 1) cand_rows<256>(w, b, a, shf4, lg, warp, lane);
            else                 cand_rows<512>(w, b, a, shf4, lg, warp, lane);
            __syncthreads();

            if (tid == 0) {
                float px = sigf(lg[0]), py = sigf(lg[1]);
                float pw = sigf(lg[2]), ph = sigf(lg[3]);
                s_obj = sigf(lg[4]);
                int gx = hw % W, gy = hw / W;
                float2 anc = c_anchors[level][a];
                float cx = (2.f * px - 0.5f + (float)gx) * stride;
                float cy = (2.f * py - 0.5f + (float)gy) * stride;
                float bw = 4.f * pw * pw * anc.x;
                float bh = 4.f * ph * ph * anc.y;
                float x1 = cx - 0.5f * bw, y1 = cy - 0.5f * bh;
                float x2 = cx + 0.5f * bw, y2 = cy + 0.5f * bh;
                x1 = fminf(fmaxf(x1, 0.f), IMGF);
                y1 = fminf(fmaxf(y1, 0.f), IMGF);
                x2 = fminf(fmaxf(x2, 0.f), IMGF);
                y2 = fminf(fmaxf(y2, 0.f), IMGF);
                s_box = make_float4(x1, y1, x2, y2);
            }
            __syncthreads();

            if (tid < NUM_CLASSES) {
                float ob = s_obj;
                if (ob > SCORE_T) {
                    float s = ob * sigf(lg[5 + tid]);
                    if (s > SCORE_T) {
                        int pos = atomicAdd(&g_cnt[1 + n], 1);
                        if (pos < DCAP) {
                            g_detScore[n][pos] = s;
                            g_detBox[n][pos]   = s_box;
                            g_detInfo[n][pos]  = (aoff + hw * 3 + a) * NUM_CLASSES + tid;
                        }
                    }
                }
            }
            __syncthreads();
        }
    }

    // ---------- global arrive; non-NMS blocks exit (deadlock-free: waiters hold only 8 SMs) ----------
    __syncthreads();
    if (tid == 0) { __threadfence(); atomicAdd(&g_barA, 1); }
    if (blockIdx.x >= NIMG) return;
    if (tid == 0) {
        while (ld_acq(&g_barA) < CN_GRID) __nanosleep(128);
        __threadfence();
    }
    __syncthreads();

    // ---------- nms phase (blocks 0..7) ----------
    {
        unsigned long long* keys = (unsigned long long*)dyn;       // 1024 * 8
        int*    payload = (int*)   (dyn + 8192);                   // 1024 * 4
        float4* box     = (float4*)(dyn + 12288);                  // 1024 * 16
        float*  scr     = (float*) (dyn + 28672);                  // 1024 * 4
        int*    lab     = (int*)   (dyn + 32768);                  // 1024 * 4
        int*    val     = (int*)   (dyn + 36864);                  // 1024 * 4
        __shared__ int picks[DET];
        __shared__ int s_sel, s_np, s_M;

        int n = blockIdx.x;
        if (tid == 0) { s_np = 0; s_M = ld_acq(&g_cnt[1 + n]); }
        __syncthreads();
        int M = s_M;
        if (M > DCAP) M = DCAP;

        if (M > 0) {
            int sortN = 2;
            while (sortN < M) sortN <<= 1;

            for (int i = tid; i < sortN; i += 256) {
                if (i < M) {
                    unsigned u = __float_as_uint(g_detScore[n][i]);
                    u = (u & 0x80000000u) ? ~u : (u | 0x80000000u);
                    keys[i] = ((unsigned long long)u << 32) | (unsigned)(0x7FFFFFFF - g_detInfo[n][i]);
                    payload[i] = i;
                } else {
                    keys[i] = 0ULL;
                    payload[i] = -1;
                }
            }
            __syncthreads();

            for (int k = 2; k <= sortN; k <<= 1) {
                for (int j = k >> 1; j > 0; j >>= 1) {
                    for (int i = tid; i < sortN; i += 256) {
                        int ixj = i ^ j;
                        if (ixj > i) {
                            bool up = ((i & k) == 0);
                            unsigned long long ka = keys[i], kb = keys[ixj];
                            bool sw = up ? (ka < kb) : (ka > kb);
                            if (sw) {
                                keys[i] = kb; keys[ixj] = ka;
                                int p = payload[i]; payload[i] = payload[ixj]; payload[ixj] = p;
                            }
                        }
                    }
                    __syncthreads();
                }
            }

            int M2 = M < TOPK ? M : TOPK;
            for (int i = tid; i < M2; i += 256) {
                int ci = payload[i];
                box[i] = g_detBox[n][ci];
                scr[i] = g_detScore[n][ci];
                lab[i] = g_detInfo[n][ci] % NUM_CLASSES;
                val[i] = 1;
            }
            __syncthreads();

            int cursor = 0;
            for (int iter = 0; iter < DET; iter++) {
                if (tid == 0) {
                    int sel = -1;
                    for (int j = cursor; j < M2; j++)
                        if (val[j]) { sel = j; break; }
                    s_sel = sel;
                    if (sel >= 0) {
                        picks[iter] = sel;
                        val[sel] = 0;
                        s_np = iter + 1;
                        cursor = sel + 1;
                    }
                }
                __syncthreads();
                int sel = s_sel;
                if (sel < 0) break;
                float4 bs = box[sel];
                int ls = lab[sel];
                float areaS = (bs.z - bs.x) * (bs.w - bs.y);
                for (int j = tid; j < M2; j += 256) {
                    if (val[j] && lab[j] == ls) {
                        float4 bj = box[j];
                        float ix1 = fmaxf(bs.x, bj.x), iy1 = fmaxf(bs.y, bj.y);
                        float ix2 = fminf(bs.z, bj.z), iy2 = fminf(bs.w, bj.w);
                        float iw = fmaxf(ix2 - ix1, 0.f), ih = fmaxf(iy2 - iy1, 0.f);
                        float inter = iw * ih;
                        float aj = (bj.z - bj.x) * (bj.w - bj.y);
                        float iou = inter / (areaS + aj - inter + 1e-7f);
                        if (iou > NMS_T) val[j] = 0;
                    }
                }
                __syncthreads();
            }
            __syncthreads();
        }
        __syncthreads();

        int np = s_np;
        float s = __ldg(sf + n);
        for (int d = tid; d < DET; d += 256) {
            float o0 = 0, o1 = 0, o2 = 0, o3 = 0, o4 = 0, o5 = 0;
            if (d < np) {
                int p = picks[d];
                float4 bbv = box[p];
                o0 = bbv.x / s; o1 = bbv.y / s; o2 = bbv.z / s; o3 = bbv.w / s;
                o4 = scr[p];
                o5 = (float)lab[p];
            }
            float* po = out + ((size_t)n * DET + d) * 6;
            po[0] = o0; po[1] = o1; po[2] = o2; po[3] = o3; po[4] = o4; po[5] = o5;
        }

        // -------- reset counters for next graph replay --------
        __syncthreads();
        if (tid == 0) {
            g_cnt[1 + n] = 0;
            __threadfence();
            atomicAdd(&g_barB, 1);
            if (n == 0) {
                while (ld_acq(&g_barB) < NIMG) __nanosleep(128);
                g_cnt[0] = 0;
                g_barA = 0;
                g_barB = 0;
            }
        }
    }
}

// ---------------- launch ----------------
extern "C" void kernel_launch(void* const* d_in, const int* in_sizes, int n_in,
                              void* d_out, int out_size)
{
    const float *f0 = nullptr, *f1 = nullptr, *f2 = nullptr;
    const float *w0 = nullptr, *w1 = nullptr, *w2 = nullptr;
    const float *bbp[3] = {nullptr, nullptr, nullptr};
    const float *sf = nullptr;
    int bcount = 0;
    for (int i = 0; i < n_in; i++) {
        const float* p = (const float*)d_in[i];
        switch (in_sizes[i]) {
            case 6553600: f0 = p; break;
            case 3276800: f1 = p; break;
            case 1638400: f2 = p; break;
            case 32640:   w0 = p; break;
            case 65280:   w1 = p; break;
            case 130560:  w2 = p; break;
            case 255:     if (bcount < 3) bbp[bcount++] = p; break;
            case 8:       sf = p; break;
            default: break;
        }
    }
    const float *b0 = bbp[0], *b1 = bbp[1], *b2 = bbp[2];
    float* out = (float*)d_out;

    obj_kernel<<<OBJ_BLOCKS, 256>>>(f0, f1, f2, w0, w1, w2, b0, b1, b2);

    cudaFuncSetAttribute(candnms_kernel, cudaFuncAttributeMaxDynamicSharedMemorySize, CN_SMEM);
    candnms_kernel<<<CN_GRID, 256, CN_SMEM>>>(f0, f1, f2, w0, w1, w2, b0, b1, b2, sf, out);
}